// round 13
// baseline (speedup 1.0000x reference)
#include <cuda_runtime.h>
#include <cuda_bf16.h>
#include <math.h>
#include <stdint.h>

// Problem constants
#define B_    1024
#define H_    512
#define V_    2048
#define T_    32
#define G4H   2048          // 4*H
#define NTOT  4096          // 4H + V
#define K3    1536          // 3*H  (bf16x3 split-K, logits path only)

// bf16 logits tiling: 128x128 tile, BK=32, 256 threads
#define LPAD  40                      // smem row stride in halves (80B), conflict-free
#define LBUF  (128 * LPAD)            // 5120 halves per tile buffer
#define SMEM_BYTES (4 * LBUF * 2)     // 40960 B (also covers fp32 path's 16KB)

#define NCAND 4

// ---------------- persistent device state / scratch (no allocs allowed) ----
__device__ float g_h[B_ * H_];                 // h_t (fp32, bit-exact trajectory)
__device__ float g_c[B_ * H_];                 // c_t
__device__ float g_gatepre[B_ * G4H];          // h@W_hh^T pre-activation (fp32)
__device__ float g_Wc[NTOT * H_];              // [W_hh ; W_out] row-major [N][K]
__device__ float g_WihT[V_ * G4H];             // W_ih^T (one-hot gather rows)
__device__ __nv_bfloat16 g_Am[B_ * K3];        // h split  m-major: [hi|lo|hi]
__device__ __nv_bfloat16 g_Bl[V_ * K3];        // W_out split n-major: [Hi|Hi|Lo]
__device__ int   g_p[B_];                      // argmax indices
__device__ float g_mask[B_];                   // running mask

// ---------------------------------------------------------------- helpers
__device__ __forceinline__ float sigm(float x) { return 1.0f / (1.0f + expf(-x)); }

__device__ __forceinline__ void cp_async16(__nv_bfloat16* dst, const __nv_bfloat16* src) {
    uint32_t d = (uint32_t)__cvta_generic_to_shared(dst);
    asm volatile("cp.async.cg.shared.global [%0], [%1], 16;\n" :: "r"(d), "l"(src));
}

// ------------------------------------------------------------- init state
__global__ void init_kernel(const float* __restrict__ enc_h,
                            const float* __restrict__ enc_c) {
    int idx = blockIdx.x * blockDim.x + threadIdx.x;
    if (idx < B_ * H_) {
        g_h[idx] = enc_h[idx];
        g_c[idx] = enc_c[idx];
    }
    if (idx < B_) {
        g_mask[idx] = 1.0f;
        g_p[idx] = 0;
    }
}

// --------------------------------------------- build Wc = [W_hh ; W_out]
__global__ void build_wc_kernel(const float* __restrict__ W_hh,
                                const float* __restrict__ W_out) {
    int idx = blockIdx.x * blockDim.x + threadIdx.x;
    const int c4_per_row = H_ / 4;
    if (idx >= NTOT * c4_per_row) return;
    int row = idx / c4_per_row;
    int c4  = idx - row * c4_per_row;
    float4 v;
    if (row < G4H)
        v = *(const float4*)(W_hh + (size_t)row * H_ + c4 * 4);
    else
        v = *(const float4*)(W_out + (size_t)(row - G4H) * H_ + c4 * 4);
    *(float4*)(g_Wc + (size_t)row * H_ + c4 * 4) = v;
}

// ------------------------------------------------ transpose W_ih -> WihT
__global__ void transpose_kernel(const float* __restrict__ W) {
    __shared__ float tile[32][33];
    int x = blockIdx.x * 32 + threadIdx.x;
    int y = blockIdx.y * 32 + threadIdx.y;
#pragma unroll
    for (int j = 0; j < 32; j += 8)
        tile[threadIdx.y + j][threadIdx.x] = W[(size_t)(y + j) * V_ + x];
    __syncthreads();
    int x2 = blockIdx.y * 32 + threadIdx.x;
    int y2 = blockIdx.x * 32 + threadIdx.y;
#pragma unroll
    for (int j = 0; j < 32; j += 8)
        g_WihT[(size_t)(y2 + j) * G4H + x2] = tile[threadIdx.x][threadIdx.y + j];
}

// ---------------- W_out rows -> B' n-major [2048][1536]: segs [Hi|Hi|Lo]
__global__ void convert_w_kernel() {
    int idx = blockIdx.x * blockDim.x + threadIdx.x;   // over V_*H_
    if (idx >= V_ * H_) return;
    int n = idx >> 9;
    int k = idx & (H_ - 1);
    float w = g_Wc[(size_t)(G4H + n) * H_ + k];
    __nv_bfloat16 hi = __float2bfloat16_rn(w);
    __nv_bfloat16 lo = __float2bfloat16_rn(w - __bfloat162float(hi));
    __nv_bfloat16* row = g_Bl + (size_t)n * K3;
    row[0 * H_ + k] = hi;
    row[1 * H_ + k] = hi;
    row[2 * H_ + k] = lo;
}

// ---------------- h -> A' m-major [1024][1536]: segs [hi|lo|hi]
// products: hi*Hi + lo*Hi + hi*Lo  (dropped lo*Lo ~2^-16 rel)
__device__ __forceinline__ void write_a_split(int b, int i, float x) {
    __nv_bfloat16 hi = __float2bfloat16_rn(x);
    __nv_bfloat16 lo = __float2bfloat16_rn(x - __bfloat162float(hi));
    __nv_bfloat16* row = g_Am + (size_t)b * K3;
    row[0 * H_ + i] = hi;
    row[1 * H_ + i] = lo;
    row[2 * H_ + i] = hi;
}

// ================================================================ DUAL GEMM
// blocks [0,128):   fp32 SIMT gate GEMM   gatepre = h @ W_hh^T
//                   (VERBATIM round-2 arithmetic: ascending-k fmaf chain)
// blocks [128,256): bf16x3 tensor GEMM    logits  = h @ W_out^T + b_out
__global__ __launch_bounds__(256, 2)
void dual_kernel(const float* __restrict__ bout,
                 float* __restrict__ logits) {
    extern __shared__ char smraw[];
    const int tid = threadIdx.x;

    if (blockIdx.x < 128) {
        // ---------------- fp32 gate path (bit-exact round-2 math) ----------
        float* As = (float*)smraw;        // [16][128]
        float* Bs = As + 16 * 128;        // [16][128]

        const int m0 = (blockIdx.x >> 4) * 128;
        const int n0 = (blockIdx.x & 15) * 128;

        const float* Arow = g_h  + (size_t)m0 * H_;
        const float* Brow = g_Wc + (size_t)n0 * H_;

        const int lr = tid >> 2;
        const int lc = (tid & 3) * 4;

        float4 a0r = *(const float4*)(Arow + (size_t)lr        * H_ + lc);
        float4 a1r = *(const float4*)(Arow + (size_t)(lr + 64) * H_ + lc);
        float4 b0r = *(const float4*)(Brow + (size_t)lr        * H_ + lc);
        float4 b1r = *(const float4*)(Brow + (size_t)(lr + 64) * H_ + lc);

        float acc[8][8];
#pragma unroll
        for (int i = 0; i < 8; i++)
#pragma unroll
            for (int j = 0; j < 8; j++) acc[i][j] = 0.0f;

        const int tRow = (tid >> 4) * 4;
        const int tCol = (tid & 15) * 4;

        const int KT = H_ / 16;
        for (int kt = 0; kt < KT; kt++) {
            As[(lc + 0) * 128 + lr]      = a0r.x; As[(lc + 1) * 128 + lr]      = a0r.y;
            As[(lc + 2) * 128 + lr]      = a0r.z; As[(lc + 3) * 128 + lr]      = a0r.w;
            As[(lc + 0) * 128 + lr + 64] = a1r.x; As[(lc + 1) * 128 + lr + 64] = a1r.y;
            As[(lc + 2) * 128 + lr + 64] = a1r.z; As[(lc + 3) * 128 + lr + 64] = a1r.w;
            Bs[(lc + 0) * 128 + lr]      = b0r.x; Bs[(lc + 1) * 128 + lr]      = b0r.y;
            Bs[(lc + 2) * 128 + lr]      = b0r.z; Bs[(lc + 3) * 128 + lr]      = b0r.w;
            Bs[(lc + 0) * 128 + lr + 64] = b1r.x; Bs[(lc + 1) * 128 + lr + 64] = b1r.y;
            Bs[(lc + 2) * 128 + lr + 64] = b1r.z; Bs[(lc + 3) * 128 + lr + 64] = b1r.w;
            __syncthreads();

            if (kt + 1 < KT) {
                int k0 = (kt + 1) * 16;
                a0r = *(const float4*)(Arow + (size_t)lr        * H_ + k0 + lc);
                a1r = *(const float4*)(Arow + (size_t)(lr + 64) * H_ + k0 + lc);
                b0r = *(const float4*)(Brow + (size_t)lr        * H_ + k0 + lc);
                b1r = *(const float4*)(Brow + (size_t)(lr + 64) * H_ + k0 + lc);
            }

#pragma unroll
            for (int k = 0; k < 16; k++) {
                float4 av0 = *(const float4*)&As[k * 128 + tRow];
                float4 av1 = *(const float4*)&As[k * 128 + tRow + 64];
                float4 bv0 = *(const float4*)&Bs[k * 128 + tCol];
                float4 bv1 = *(const float4*)&Bs[k * 128 + tCol + 64];
                float a[8] = {av0.x, av0.y, av0.z, av0.w, av1.x, av1.y, av1.z, av1.w};
                float b[8] = {bv0.x, bv0.y, bv0.z, bv0.w, bv1.x, bv1.y, bv1.z, bv1.w};
#pragma unroll
                for (int i = 0; i < 8; i++)
#pragma unroll
                    for (int j = 0; j < 8; j++)
                        acc[i][j] = fmaf(a[i], b[j], acc[i][j]);
            }
            __syncthreads();
        }

#pragma unroll
        for (int ih = 0; ih < 2; ih++) {
#pragma unroll
            for (int i = 0; i < 4; i++) {
                int row = m0 + tRow + ih * 64 + i;
#pragma unroll
                for (int jh = 0; jh < 2; jh++) {
                    int col = n0 + tCol + jh * 64;
                    float4 v;
                    v.x = acc[ih * 4 + i][jh * 4 + 0];
                    v.y = acc[ih * 4 + i][jh * 4 + 1];
                    v.z = acc[ih * 4 + i][jh * 4 + 2];
                    v.w = acc[ih * 4 + i][jh * 4 + 3];
                    *(float4*)(g_gatepre + (size_t)row * G4H + col) = v;
                }
            }
        }
    } else {
        // ---------------- bf16x3 tensor logits path ------------------------
        __nv_bfloat16* sm = (__nv_bfloat16*)smraw;
        const int l    = blockIdx.x - 128;
        const int m0   = (l >> 4) * 128;
        const int n0   = (l & 15) * 128;
        const int lane = tid & 31;
        const int warp = tid >> 5;
        const int g    = lane >> 2;
        const int q    = lane & 3;
        const int wm   = warp >> 2;       // 0..1 (64-row strip)
        const int wn   = warp & 3;        // 0..3 (32-col strip)

        float acc[4][4][4];
#pragma unroll
        for (int i = 0; i < 4; i++)
#pragma unroll
            for (int j = 0; j < 4; j++)
#pragma unroll
                for (int r = 0; r < 4; r++) acc[i][j][r] = 0.0f;

        auto load_chunk = [&](int kt, int buf) {
            int k0 = kt * 32;
            __nv_bfloat16* Ad = sm + buf * LBUF;
            __nv_bfloat16* Bd = sm + 2 * LBUF + buf * LBUF;
#pragma unroll
            for (int i = 0; i < 2; i++) {
                int idx = tid + i * 256;
                int r   = idx >> 2;          // 0..127
                int c   = (idx & 3) * 8;     // 0,8,16,24
                cp_async16(Ad + r * LPAD + c, g_Am + (size_t)(m0 + r) * K3 + k0 + c);
                cp_async16(Bd + r * LPAD + c, g_Bl + (size_t)(n0 + r) * K3 + k0 + c);
            }
            asm volatile("cp.async.commit_group;\n" ::: "memory");
        };

        load_chunk(0, 0);

        const int KT = K3 / 32;   // 48
        for (int kt = 0; kt < KT; kt++) {
            int buf = kt & 1;
            if (kt + 1 < KT) {
                load_chunk(kt + 1, buf ^ 1);
                asm volatile("cp.async.wait_group 1;\n" ::: "memory");
            } else {
                asm volatile("cp.async.wait_group 0;\n" ::: "memory");
            }
            __syncthreads();

            const __nv_bfloat16* Ac = sm + buf * LBUF;
            const __nv_bfloat16* Bc = sm + 2 * LBUF + buf * LBUF;
            const __nv_bfloat16* aBase = Ac + (wm * 64 + g) * LPAD;
            const __nv_bfloat16* bBase = Bc + (wn * 32 + g) * LPAD;

#pragma unroll
            for (int ks = 0; ks < 2; ks++) {
                int kk = ks * 16;
                uint32_t af[4][4], bf4[4][2];
#pragma unroll
                for (int mf = 0; mf < 4; mf++) {
                    const __nv_bfloat16* ar = aBase + mf * 16 * LPAD + kk;
                    af[mf][0] = *(const uint32_t*)(ar + 2 * q);
                    af[mf][1] = *(const uint32_t*)(ar + 8 * LPAD + 2 * q);
                    af[mf][2] = *(const uint32_t*)(ar + 2 * q + 8);
                    af[mf][3] = *(const uint32_t*)(ar + 8 * LPAD + 2 * q + 8);
                }
#pragma unroll
                for (int nf = 0; nf < 4; nf++) {
                    const __nv_bfloat16* br = bBase + nf * 8 * LPAD + kk;
                    bf4[nf][0] = *(const uint32_t*)(br + 2 * q);
                    bf4[nf][1] = *(const uint32_t*)(br + 2 * q + 8);
                }
#pragma unroll
                for (int mf = 0; mf < 4; mf++)
#pragma unroll
                    for (int nf = 0; nf < 4; nf++) {
                        asm volatile(
                            "mma.sync.aligned.m16n8k16.row.col.f32.bf16.bf16.f32 "
                            "{%0,%1,%2,%3}, {%4,%5,%6,%7}, {%8,%9}, {%0,%1,%2,%3};\n"
                            : "+f"(acc[mf][nf][0]), "+f"(acc[mf][nf][1]),
                              "+f"(acc[mf][nf][2]), "+f"(acc[mf][nf][3])
                            : "r"(af[mf][0]), "r"(af[mf][1]), "r"(af[mf][2]), "r"(af[mf][3]),
                              "r"(bf4[nf][0]), "r"(bf4[nf][1]));
                    }
            }
            __syncthreads();
        }

#pragma unroll
        for (int mf = 0; mf < 4; mf++) {
            int r0 = m0 + wm * 64 + mf * 16 + g;
            int r1 = r0 + 8;
#pragma unroll
            for (int nf = 0; nf < 4; nf++) {
                int c = n0 + wn * 32 + nf * 8 + 2 * q;
                float2 bb = *(const float2*)(bout + c);
                *(float2*)(logits + (size_t)r0 * V_ + c) =
                    make_float2(acc[mf][nf][0] + bb.x, acc[mf][nf][1] + bb.y);
                *(float2*)(logits + (size_t)r1 * V_ + c) =
                    make_float2(acc[mf][nf][2] + bb.x, acc[mf][nf][3] + bb.y);
            }
        }
    }
}

// --------------------------------------------------------- LSTM cell step
// fp32 math bit-identical to round-2; also emits bf16 split of h
__global__ void cell_kernel(const float* __restrict__ b_ih,
                            const float* __restrict__ b_hh,
                            int use_x) {
    int idx = blockIdx.x * blockDim.x + threadIdx.x;
    if (idx >= B_ * H_) return;
    int b = idx >> 9;
    int i = idx & (H_ - 1);

    const float* gp = g_gatepre + (size_t)b * G4H;
    float xi = 0.f, xf = 0.f, xg = 0.f, xo = 0.f;
    if (use_x) {
        const float* xr = g_WihT + (size_t)g_p[b] * G4H;
        xi = xr[i]; xf = xr[H_ + i]; xg = xr[2 * H_ + i]; xo = xr[3 * H_ + i];
    }
    float gi = gp[i]          + b_ih[i]          + b_hh[i]          + xi;
    float gf = gp[H_ + i]     + b_ih[H_ + i]     + b_hh[H_ + i]     + xf;
    float gg = gp[2 * H_ + i] + b_ih[2 * H_ + i] + b_hh[2 * H_ + i] + xg;
    float go = gp[3 * H_ + i] + b_ih[3 * H_ + i] + b_hh[3 * H_ + i] + xo;

    float cn = sigm(gf) * g_c[idx] + sigm(gi) * tanhf(gg);
    float hn = sigm(go) * tanhf(cn);
    g_c[idx] = cn;
    g_h[idx] = hn;
    write_a_split(b, i, hn);
}

// ------------------------------ decide: top-NCAND select + fp32-seq recompute
// phase 1: top-4 candidates from bf16x3 logits (noise 1.5e-5 << gaps)
// phase 2: recompute candidate logits with sequential ascending-k fp32 fmaf
//          over g_h * g_Wc[W_out row] + b_out  (round-2 exact arithmetic)
// phase 3: winner, first-index tie-break
__global__ void decide_kernel(const float* __restrict__ logits_t,
                              const float* __restrict__ bout,
                              float* __restrict__ pred_t,
                              float* __restrict__ mask_t) {
    __shared__ float srow[V_];
    __shared__ float sv[256];
    __shared__ int   si[256];
    __shared__ int   cand[NCAND];
    __shared__ float cval[NCAND];

    int b   = blockIdx.x;
    int tid = threadIdx.x;
    const float* row = logits_t + (size_t)b * V_;

    for (int j = tid; j < V_; j += 256) srow[j] = row[j];
    __syncthreads();

    for (int p = 0; p < NCAND; p++) {
        float bv = -INFINITY;
        int   bi = V_;
        for (int j = tid; j < V_; j += 256) {
            bool skip = false;
            for (int q = 0; q < p; q++) skip |= (j == cand[q]);
            if (skip) continue;
            float v = srow[j];
            if (v > bv || (v == bv && j < bi)) { bv = v; bi = j; }
        }
        sv[tid] = bv; si[tid] = bi;
        __syncthreads();
        for (int s = 128; s > 0; s >>= 1) {
            if (tid < s) {
                if (sv[tid + s] > sv[tid] ||
                    (sv[tid + s] == sv[tid] && si[tid + s] < si[tid])) {
                    sv[tid] = sv[tid + s];
                    si[tid] = si[tid + s];
                }
            }
            __syncthreads();
        }
        if (tid == 0) cand[p] = si[0];
        __syncthreads();
    }

    if (tid < NCAND) {
        int c = cand[tid];
        const float* hr = g_h  + (size_t)b * H_;
        const float* wr = g_Wc + (size_t)(G4H + c) * H_;
        float acc = 0.0f;
        for (int k = 0; k < H_; k++)
            acc = fmaf(hr[k], wr[k], acc);
        cval[tid] = acc + bout[c];
    }
    __syncthreads();

    if (tid == 0) {
        float bv = cval[0];
        int   bi = cand[0];
        for (int p = 1; p < NCAND; p++) {
            if (cval[p] > bv || (cval[p] == bv && cand[p] < bi)) {
                bv = cval[p];
                bi = cand[p];
            }
        }
        g_p[b] = bi;
        pred_t[(size_t)b * V_ + bi] = 1.0f;
        mask_t[b] = g_mask[b];
        if (bi == 0) g_mask[b] = 0.0f;
    }
}

// ---------------------------------------------------------------- driver
extern "C" void kernel_launch(void* const* d_in, const int* in_sizes, int n_in,
                              void* d_out, int out_size) {
    const float* enc_h = (const float*)d_in[0];
    const float* enc_c = (const float*)d_in[1];
    const float* W_ih  = (const float*)d_in[2];
    const float* W_hh  = (const float*)d_in[3];
    const float* b_ih  = (const float*)d_in[4];
    const float* b_hh  = (const float*)d_in[5];
    const float* W_out = (const float*)d_in[6];
    const float* b_out = (const float*)d_in[7];
    (void)in_sizes; (void)n_in; (void)out_size;

    float* out      = (float*)d_out;
    const size_t TBV = (size_t)T_ * B_ * V_;
    float* predicts = out;               // [T,B,V]
    float* logits   = out + TBV;         // [T,B,V]
    float* masks    = out + 2 * TBV;     // [T,1,B]

    cudaMemsetAsync(predicts, 0, TBV * sizeof(float));

    init_kernel<<<(B_ * H_ + 255) / 256, 256>>>(enc_h, enc_c);
    build_wc_kernel<<<(NTOT * (H_ / 4) + 255) / 256, 256>>>(W_hh, W_out);
    transpose_kernel<<<dim3(V_ / 32, G4H / 32), dim3(32, 8)>>>(W_ih);
    convert_w_kernel<<<(V_ * H_ + 255) / 256, 256>>>();

    // prologue: gatepre_0 = enc_h @ W_hh^T  (gate blocks only)
    dual_kernel<<<128, 256, SMEM_BYTES>>>(b_out, logits /*unused*/);

    for (int t = 0; t < T_; t++) {
        // h_t, c_t (fp32 exact) + bf16 split of h_t
        cell_kernel<<<(B_ * H_ + 255) / 256, 256>>>(b_ih, b_hh, t > 0 ? 1 : 0);
        // fused dual-pipe: gatepre_{t+1} (fp32 fma pipe) || logits_t (tensor pipe)
        dual_kernel<<<256, 256, SMEM_BYTES>>>(
            b_out, logits + (size_t)t * B_ * V_);
        // decision: candidates from bf16 logits, fp32-exact recompute
        decide_kernel<<<B_, 256>>>(logits + (size_t)t * B_ * V_, b_out,
                                   predicts + (size_t)t * B_ * V_,
                                   masks + (size_t)t * B_);
    }
}

// round 14
// speedup vs baseline: 1.0532x; 1.0532x over previous
#include <cuda_runtime.h>
#include <cuda_bf16.h>
#include <math.h>
#include <stdint.h>

// Problem constants
#define B_    1024
#define H_    512
#define V_    2048
#define T_    32
#define G4H   2048          // 4*H
#define NTOT  4096          // 4H + V
#define K3    1536          // 3*H  (bf16x3 split-K, logits path only)

// bf16 logits tiling: 128x128 tile, BK=64, 256 threads
#define PADH  72                      // smem row stride in halves (144B)
#define LBUF  (128 * PADH)            // 9216 halves per tile buffer
#define SMEM_BYTES (4 * LBUF * 2)     // 73728 B (covers fp32 path's 16KB too)

#define MARGIN 2e-3f
#define MAXCAND 32

// ---------------- persistent device state / scratch (no allocs allowed) ----
__device__ float g_h[B_ * H_];                 // h_t (fp32, bit-exact trajectory)
__device__ float g_c[B_ * H_];                 // c_t
__device__ float g_gatepre[B_ * G4H];          // h@W_hh^T pre-activation (fp32)
__device__ float g_Wc[NTOT * H_];              // [W_hh ; W_out] row-major [N][K]
__device__ float g_WihT[V_ * G4H];             // W_ih^T (one-hot gather rows)
__device__ __nv_bfloat16 g_Am[B_ * K3];        // h split  m-major: [hi|lo|hi]
__device__ __nv_bfloat16 g_Bl[V_ * K3];        // W_out split n-major: [Hi|Hi|Lo]
__device__ int   g_p[B_];                      // argmax indices
__device__ float g_mask[B_];                   // running mask

// ---------------------------------------------------------------- helpers
__device__ __forceinline__ float sigm(float x) { return 1.0f / (1.0f + expf(-x)); }

__device__ __forceinline__ void cp_async16(__nv_bfloat16* dst, const __nv_bfloat16* src) {
    uint32_t d = (uint32_t)__cvta_generic_to_shared(dst);
    asm volatile("cp.async.cg.shared.global [%0], [%1], 16;\n" :: "r"(d), "l"(src));
}

// ------------------------------------------------------------- init state
__global__ void init_kernel(const float* __restrict__ enc_h,
                            const float* __restrict__ enc_c) {
    int idx = blockIdx.x * blockDim.x + threadIdx.x;
    if (idx < B_ * H_) {
        g_h[idx] = enc_h[idx];
        g_c[idx] = enc_c[idx];
    }
    if (idx < B_) {
        g_mask[idx] = 1.0f;
        g_p[idx] = 0;
    }
}

// --------------------------------------------- build Wc = [W_hh ; W_out]
__global__ void build_wc_kernel(const float* __restrict__ W_hh,
                                const float* __restrict__ W_out) {
    int idx = blockIdx.x * blockDim.x + threadIdx.x;
    const int c4_per_row = H_ / 4;
    if (idx >= NTOT * c4_per_row) return;
    int row = idx / c4_per_row;
    int c4  = idx - row * c4_per_row;
    float4 v;
    if (row < G4H)
        v = *(const float4*)(W_hh + (size_t)row * H_ + c4 * 4);
    else
        v = *(const float4*)(W_out + (size_t)(row - G4H) * H_ + c4 * 4);
    *(float4*)(g_Wc + (size_t)row * H_ + c4 * 4) = v;
}

// ------------------------------------------------ transpose W_ih -> WihT
__global__ void transpose_kernel(const float* __restrict__ W) {
    __shared__ float tile[32][33];
    int x = blockIdx.x * 32 + threadIdx.x;
    int y = blockIdx.y * 32 + threadIdx.y;
#pragma unroll
    for (int j = 0; j < 32; j += 8)
        tile[threadIdx.y + j][threadIdx.x] = W[(size_t)(y + j) * V_ + x];
    __syncthreads();
    int x2 = blockIdx.y * 32 + threadIdx.x;
    int y2 = blockIdx.x * 32 + threadIdx.y;
#pragma unroll
    for (int j = 0; j < 32; j += 8)
        g_WihT[(size_t)(y2 + j) * G4H + x2] = tile[threadIdx.x][threadIdx.y + j];
}

// ---------------- W_out rows -> B' n-major [2048][1536]: segs [Hi|Hi|Lo]
__global__ void convert_w_kernel() {
    int idx = blockIdx.x * blockDim.x + threadIdx.x;   // over V_*H_
    if (idx >= V_ * H_) return;
    int n = idx >> 9;
    int k = idx & (H_ - 1);
    float w = g_Wc[(size_t)(G4H + n) * H_ + k];
    __nv_bfloat16 hi = __float2bfloat16_rn(w);
    __nv_bfloat16 lo = __float2bfloat16_rn(w - __bfloat162float(hi));
    __nv_bfloat16* row = g_Bl + (size_t)n * K3;
    row[0 * H_ + k] = hi;
    row[1 * H_ + k] = hi;
    row[2 * H_ + k] = lo;
}

// ---------------- h -> A' m-major [1024][1536]: segs [hi|lo|hi]
// products: hi*Hi + lo*Hi + hi*Lo  (dropped lo*Lo ~2^-18 per term)
__device__ __forceinline__ void write_a_split(int b, int i, float x) {
    __nv_bfloat16 hi = __float2bfloat16_rn(x);
    __nv_bfloat16 lo = __float2bfloat16_rn(x - __bfloat162float(hi));
    __nv_bfloat16* row = g_Am + (size_t)b * K3;
    row[0 * H_ + i] = hi;
    row[1 * H_ + i] = lo;
    row[2 * H_ + i] = hi;
}

// ================================================================ DUAL GEMM
// blocks [0,128):   fp32 SIMT gate GEMM   gatepre = h @ W_hh^T
//                   (VERBATIM round-2 arithmetic: ascending-k fmaf chain)
// blocks [128,256): bf16x3 tensor GEMM    logits  = h @ W_out^T + b_out
__global__ __launch_bounds__(256, 2)
void dual_kernel(const float* __restrict__ bout,
                 float* __restrict__ logits) {
    extern __shared__ char smraw[];
    const int tid = threadIdx.x;

    if (blockIdx.x < 128) {
        // ---------------- fp32 gate path (bit-exact round-2 math) ----------
        float* As = (float*)smraw;        // [16][128]
        float* Bs = As + 16 * 128;        // [16][128]

        const int m0 = (blockIdx.x >> 4) * 128;
        const int n0 = (blockIdx.x & 15) * 128;

        const float* Arow = g_h  + (size_t)m0 * H_;
        const float* Brow = g_Wc + (size_t)n0 * H_;

        const int lr = tid >> 2;
        const int lc = (tid & 3) * 4;

        float4 a0r = *(const float4*)(Arow + (size_t)lr        * H_ + lc);
        float4 a1r = *(const float4*)(Arow + (size_t)(lr + 64) * H_ + lc);
        float4 b0r = *(const float4*)(Brow + (size_t)lr        * H_ + lc);
        float4 b1r = *(const float4*)(Brow + (size_t)(lr + 64) * H_ + lc);

        float acc[8][8];
#pragma unroll
        for (int i = 0; i < 8; i++)
#pragma unroll
            for (int j = 0; j < 8; j++) acc[i][j] = 0.0f;

        const int tRow = (tid >> 4) * 4;
        const int tCol = (tid & 15) * 4;

        const int KT = H_ / 16;
        for (int kt = 0; kt < KT; kt++) {
            As[(lc + 0) * 128 + lr]      = a0r.x; As[(lc + 1) * 128 + lr]      = a0r.y;
            As[(lc + 2) * 128 + lr]      = a0r.z; As[(lc + 3) * 128 + lr]      = a0r.w;
            As[(lc + 0) * 128 + lr + 64] = a1r.x; As[(lc + 1) * 128 + lr + 64] = a1r.y;
            As[(lc + 2) * 128 + lr + 64] = a1r.z; As[(lc + 3) * 128 + lr + 64] = a1r.w;
            Bs[(lc + 0) * 128 + lr]      = b0r.x; Bs[(lc + 1) * 128 + lr]      = b0r.y;
            Bs[(lc + 2) * 128 + lr]      = b0r.z; Bs[(lc + 3) * 128 + lr]      = b0r.w;
            Bs[(lc + 0) * 128 + lr + 64] = b1r.x; Bs[(lc + 1) * 128 + lr + 64] = b1r.y;
            Bs[(lc + 2) * 128 + lr + 64] = b1r.z; Bs[(lc + 3) * 128 + lr + 64] = b1r.w;
            __syncthreads();

            if (kt + 1 < KT) {
                int k0 = (kt + 1) * 16;
                a0r = *(const float4*)(Arow + (size_t)lr        * H_ + k0 + lc);
                a1r = *(const float4*)(Arow + (size_t)(lr + 64) * H_ + k0 + lc);
                b0r = *(const float4*)(Brow + (size_t)lr        * H_ + k0 + lc);
                b1r = *(const float4*)(Brow + (size_t)(lr + 64) * H_ + k0 + lc);
            }

#pragma unroll
            for (int k = 0; k < 16; k++) {
                float4 av0 = *(const float4*)&As[k * 128 + tRow];
                float4 av1 = *(const float4*)&As[k * 128 + tRow + 64];
                float4 bv0 = *(const float4*)&Bs[k * 128 + tCol];
                float4 bv1 = *(const float4*)&Bs[k * 128 + tCol + 64];
                float a[8] = {av0.x, av0.y, av0.z, av0.w, av1.x, av1.y, av1.z, av1.w};
                float b[8] = {bv0.x, bv0.y, bv0.z, bv0.w, bv1.x, bv1.y, bv1.z, bv1.w};
#pragma unroll
                for (int i = 0; i < 8; i++)
#pragma unroll
                    for (int j = 0; j < 8; j++)
                        acc[i][j] = fmaf(a[i], b[j], acc[i][j]);
            }
            __syncthreads();
        }

#pragma unroll
        for (int ih = 0; ih < 2; ih++) {
#pragma unroll
            for (int i = 0; i < 4; i++) {
                int row = m0 + tRow + ih * 64 + i;
#pragma unroll
                for (int jh = 0; jh < 2; jh++) {
                    int col = n0 + tCol + jh * 64;
                    float4 v;
                    v.x = acc[ih * 4 + i][jh * 4 + 0];
                    v.y = acc[ih * 4 + i][jh * 4 + 1];
                    v.z = acc[ih * 4 + i][jh * 4 + 2];
                    v.w = acc[ih * 4 + i][jh * 4 + 3];
                    *(float4*)(g_gatepre + (size_t)row * G4H + col) = v;
                }
            }
        }
    } else {
        // ---------------- bf16x3 tensor logits path, BK=64 -----------------
        __nv_bfloat16* sm = (__nv_bfloat16*)smraw;
        const int l    = blockIdx.x - 128;
        const int m0   = (l >> 4) * 128;
        const int n0   = (l & 15) * 128;
        const int lane = tid & 31;
        const int warp = tid >> 5;
        const int g    = lane >> 2;
        const int q    = lane & 3;
        const int wm   = warp >> 2;       // 0..1 (64-row strip)
        const int wn   = warp & 3;        // 0..3 (32-col strip)

        float acc[4][4][4];
#pragma unroll
        for (int i = 0; i < 4; i++)
#pragma unroll
            for (int j = 0; j < 4; j++)
#pragma unroll
                for (int r = 0; r < 4; r++) acc[i][j][r] = 0.0f;

        auto load_chunk = [&](int kt, int buf) {
            int k0 = kt * 64;
            __nv_bfloat16* Ad = sm + buf * LBUF;
            __nv_bfloat16* Bd = sm + 2 * LBUF + buf * LBUF;
#pragma unroll
            for (int i = 0; i < 4; i++) {
                int idx = tid + i * 256;
                int r   = idx >> 3;          // 0..127
                int c   = (idx & 7) * 8;     // 0..56
                cp_async16(Ad + r * PADH + c, g_Am + (size_t)(m0 + r) * K3 + k0 + c);
                cp_async16(Bd + r * PADH + c, g_Bl + (size_t)(n0 + r) * K3 + k0 + c);
            }
            asm volatile("cp.async.commit_group;\n" ::: "memory");
        };

        load_chunk(0, 0);

        const int KT = K3 / 64;   // 24
        for (int kt = 0; kt < KT; kt++) {
            int buf = kt & 1;
            if (kt + 1 < KT) {
                load_chunk(kt + 1, buf ^ 1);
                asm volatile("cp.async.wait_group 1;\n" ::: "memory");
            } else {
                asm volatile("cp.async.wait_group 0;\n" ::: "memory");
            }
            __syncthreads();

            const __nv_bfloat16* Ac = sm + buf * LBUF;
            const __nv_bfloat16* Bc = sm + 2 * LBUF + buf * LBUF;
            const __nv_bfloat16* aBase = Ac + (wm * 64 + g) * PADH;
            const __nv_bfloat16* bBase = Bc + (wn * 32 + g) * PADH;

#pragma unroll
            for (int ks = 0; ks < 4; ks++) {
                int kk = ks * 16;
                uint32_t af[4][4], bf4[4][2];
#pragma unroll
                for (int mf = 0; mf < 4; mf++) {
                    const __nv_bfloat16* ar = aBase + mf * 16 * PADH + kk;
                    af[mf][0] = *(const uint32_t*)(ar + 2 * q);
                    af[mf][1] = *(const uint32_t*)(ar + 8 * PADH + 2 * q);
                    af[mf][2] = *(const uint32_t*)(ar + 2 * q + 8);
                    af[mf][3] = *(const uint32_t*)(ar + 8 * PADH + 2 * q + 8);
                }
#pragma unroll
                for (int nf = 0; nf < 4; nf++) {
                    const __nv_bfloat16* br = bBase + nf * 8 * PADH + kk;
                    bf4[nf][0] = *(const uint32_t*)(br + 2 * q);
                    bf4[nf][1] = *(const uint32_t*)(br + 2 * q + 8);
                }
#pragma unroll
                for (int mf = 0; mf < 4; mf++)
#pragma unroll
                    for (int nf = 0; nf < 4; nf++) {
                        asm volatile(
                            "mma.sync.aligned.m16n8k16.row.col.f32.bf16.bf16.f32 "
                            "{%0,%1,%2,%3}, {%4,%5,%6,%7}, {%8,%9}, {%0,%1,%2,%3};\n"
                            : "+f"(acc[mf][nf][0]), "+f"(acc[mf][nf][1]),
                              "+f"(acc[mf][nf][2]), "+f"(acc[mf][nf][3])
                            : "r"(af[mf][0]), "r"(af[mf][1]), "r"(af[mf][2]), "r"(af[mf][3]),
                              "r"(bf4[nf][0]), "r"(bf4[nf][1]));
                    }
            }
            __syncthreads();
        }

#pragma unroll
        for (int mf = 0; mf < 4; mf++) {
            int r0 = m0 + wm * 64 + mf * 16 + g;
            int r1 = r0 + 8;
#pragma unroll
            for (int nf = 0; nf < 4; nf++) {
                int c = n0 + wn * 32 + nf * 8 + 2 * q;
                float2 bb = *(const float2*)(bout + c);
                *(float2*)(logits + (size_t)r0 * V_ + c) =
                    make_float2(acc[mf][nf][0] + bb.x, acc[mf][nf][1] + bb.y);
                *(float2*)(logits + (size_t)r1 * V_ + c) =
                    make_float2(acc[mf][nf][2] + bb.x, acc[mf][nf][3] + bb.y);
            }
        }
    }
}

// --------------------------------------------------------- LSTM cell (t=0)
__global__ void cell_kernel(const float* __restrict__ b_ih,
                            const float* __restrict__ b_hh) {
    int idx = blockIdx.x * blockDim.x + threadIdx.x;
    if (idx >= B_ * H_) return;
    int b = idx >> 9;
    int i = idx & (H_ - 1);

    const float* gp = g_gatepre + (size_t)b * G4H;
    float gi = gp[i]          + b_ih[i]          + b_hh[i];
    float gf = gp[H_ + i]     + b_ih[H_ + i]     + b_hh[H_ + i];
    float gg = gp[2 * H_ + i] + b_ih[2 * H_ + i] + b_hh[2 * H_ + i];
    float go = gp[3 * H_ + i] + b_ih[3 * H_ + i] + b_hh[3 * H_ + i];

    float cn = sigm(gf) * g_c[idx] + sigm(gi) * tanhf(gg);
    float hn = sigm(go) * tanhf(cn);
    g_c[idx] = cn;
    g_h[idx] = hn;
    write_a_split(b, i, hn);
}

// ============================ decide (step t) + cell (step t+1), fused
// pass 1: block max of bf16x3 logits row
// pass 2: collect all j with v >= max - MARGIN  (bf16x3 noise <= 2e-5 << MARGIN)
// recompute candidates with sequential ascending-k fp32 fmaf (round-2 exact)
// winner by (recomputed value desc, index asc) -> p, pred, mask
// tail: cell update for row b using gatepre (next step) + WihT[p]
__global__ void decidecell_kernel(const float* __restrict__ logits_t,
                                  const float* __restrict__ bout,
                                  const float* __restrict__ b_ih,
                                  const float* __restrict__ b_hh,
                                  float* __restrict__ pred_t,
                                  float* __restrict__ mask_t) {
    __shared__ float srow[V_];
    __shared__ float sred[64];
    __shared__ int   cand[MAXCAND];
    __shared__ float cval[MAXCAND];
    __shared__ int   s_cnt;
    __shared__ int   s_p;

    const int b   = blockIdx.x;
    const int tid = threadIdx.x;
    const float* row = logits_t + (size_t)b * V_;

    if (tid == 0) s_cnt = 0;
    for (int j = tid; j < V_; j += 256) srow[j] = row[j];
    __syncthreads();

    // pass 1: max value
    float m = -INFINITY;
    for (int j = tid; j < V_; j += 256) m = fmaxf(m, srow[j]);
#pragma unroll
    for (int s = 16; s > 0; s >>= 1)
        m = fmaxf(m, __shfl_xor_sync(0xFFFFFFFFu, m, s));
    if ((tid & 31) == 0) sred[tid >> 5] = m;
    __syncthreads();
    if (tid < 8) {
        float v = sred[tid];
#pragma unroll
        for (int s = 4; s > 0; s >>= 1)
            v = fmaxf(v, __shfl_xor_sync(0xFFu, v, s));
        if (tid == 0) sred[0] = v;
    }
    __syncthreads();
    const float thresh = sred[0] - MARGIN;

    // pass 2: collect candidates
    for (int j = tid; j < V_; j += 256) {
        if (srow[j] >= thresh) {
            int s = atomicAdd(&s_cnt, 1);
            if (s < MAXCAND) cand[s] = j;
        }
    }
    __syncthreads();
    const int nc = (s_cnt < MAXCAND) ? s_cnt : MAXCAND;

    // fp32 recompute (sequential ascending-k fmaf, round-2-exact)
    if (tid < nc) {
        int c = cand[tid];
        const float* hr = g_h  + (size_t)b * H_;
        const float* wr = g_Wc + (size_t)(G4H + c) * H_;
        float acc = 0.0f;
        for (int k = 0; k < H_; k++)
            acc = fmaf(hr[k], wr[k], acc);
        cval[tid] = acc + bout[c];
    }
    __syncthreads();

    if (tid == 0) {
        float bv = cval[0];
        int   bi = cand[0];
        for (int p = 1; p < nc; p++) {
            if (cval[p] > bv || (cval[p] == bv && cand[p] < bi)) {
                bv = cval[p];
                bi = cand[p];
            }
        }
        s_p = bi;
        g_p[b] = bi;
        pred_t[(size_t)b * V_ + bi] = 1.0f;
        mask_t[b] = g_mask[b];
        if (bi == 0) g_mask[b] = 0.0f;
    }
    __syncthreads();

    // ---- cell tail for next step (use_x = 1), identical arithmetic
    const int p = s_p;
    const float* gp = g_gatepre + (size_t)b * G4H;
    const float* xr = g_WihT   + (size_t)p * G4H;
    for (int i = tid; i < H_; i += 256) {
        int idx = (b << 9) + i;
        float gi = gp[i]          + b_ih[i]          + b_hh[i]          + xr[i];
        float gf = gp[H_ + i]     + b_ih[H_ + i]     + b_hh[H_ + i]     + xr[H_ + i];
        float gg = gp[2 * H_ + i] + b_ih[2 * H_ + i] + b_hh[2 * H_ + i] + xr[2 * H_ + i];
        float go = gp[3 * H_ + i] + b_ih[3 * H_ + i] + b_hh[3 * H_ + i] + xr[3 * H_ + i];

        float cn = sigm(gf) * g_c[idx] + sigm(gi) * tanhf(gg);
        float hn = sigm(go) * tanhf(cn);
        g_c[idx] = cn;
        g_h[idx] = hn;
        write_a_split(b, i, hn);
    }
}

// ---------------------------------------------------------------- driver
extern "C" void kernel_launch(void* const* d_in, const int* in_sizes, int n_in,
                              void* d_out, int out_size) {
    const float* enc_h = (const float*)d_in[0];
    const float* enc_c = (const float*)d_in[1];
    const float* W_ih  = (const float*)d_in[2];
    const float* W_hh  = (const float*)d_in[3];
    const float* b_ih  = (const float*)d_in[4];
    const float* b_hh  = (const float*)d_in[5];
    const float* W_out = (const float*)d_in[6];
    const float* b_out = (const float*)d_in[7];
    (void)in_sizes; (void)n_in; (void)out_size;

    // >48KB dynamic smem opt-in (idempotent; not a stream op)
    cudaFuncSetAttribute(dual_kernel,
                         cudaFuncAttributeMaxDynamicSharedMemorySize,
                         SMEM_BYTES);

    float* out      = (float*)d_out;
    const size_t TBV = (size_t)T_ * B_ * V_;
    float* predicts = out;               // [T,B,V]
    float* logits   = out + TBV;         // [T,B,V]
    float* masks    = out + 2 * TBV;     // [T,1,B]

    cudaMemsetAsync(predicts, 0, TBV * sizeof(float));

    init_kernel<<<(B_ * H_ + 255) / 256, 256>>>(enc_h, enc_c);
    build_wc_kernel<<<(NTOT * (H_ / 4) + 255) / 256, 256>>>(W_hh, W_out);
    transpose_kernel<<<dim3(V_ / 32, G4H / 32), dim3(32, 8)>>>(W_ih);
    convert_w_kernel<<<(V_ * H_ + 255) / 256, 256>>>();

    // prologue: gatepre_0 = enc_h @ W_hh^T, then h_0 (use_x = 0)
    dual_kernel<<<128, 256, SMEM_BYTES>>>(b_out, logits /*unused*/);
    cell_kernel<<<(B_ * H_ + 255) / 256, 256>>>(b_ih, b_hh);

    for (int t = 0; t < T_; t++) {
        // gatepre_{t+1} (fp32 fma pipe) || logits_t (tensor pipe)
        dual_kernel<<<256, 256, SMEM_BYTES>>>(
            b_out, logits + (size_t)t * B_ * V_);
        // decide step t (+ cell for step t+1)
        decidecell_kernel<<<B_, 256>>>(logits + (size_t)t * B_ * V_, b_out,
                                       b_ih, b_hh,
                                       predicts + (size_t)t * B_ * V_,
                                       masks + (size_t)t * B_);
    }
}